// round 12
// baseline (speedup 1.0000x reference)
#include <cuda_runtime.h>

// CrossNetwork: x_l = x0 * (x_l . W_l) + b_l + x_l, L=6 layers.
// Identity: x_l = alpha_l * x0 + sum_{i<l} b_i, with
//   d_l = x0 . W_l ; C_l = (sum_{i<l} b_i) . W_l
//   s_l = alpha_l * d_l + C_l ; alpha_{l+1} = alpha_l + s_l ; alpha_0 = 1
//   out = alpha_L * x0 + sum_i b_i
// ~256 MB HBM traffic.
// R9 lesson: the 5.7us serial prologue (precompute kernel + launch gap) was
// the remaining waste. R10: FULLY FUSED single kernel. Each block spans all
// D=2048 columns, so it computes its own bsum (prefix of b at its columns)
// and its own C_l: the 6 C partials join the 24 dot partials in the SAME
// 32-slot pair-merge reduction (31 shuffles, zero extra reduction cost).

#define D_DIM 2048
#define L_DIM 6
#define D_VEC (D_DIM / 4)      // 512 float4 per row
#define TPB   256
#define NWARP (TPB / 32)       // 8
#define ROWS  4                // rows per block
#define NVAL  (ROWS * L_DIM)   // 24 dot values
#define NRED  (NVAL + L_DIM)   // 30 reduced values (24 dots + 6 C)

__global__ __launch_bounds__(TPB) void cross_kernel(
    const float* __restrict__ x, const float* __restrict__ W,
    const float* __restrict__ b, float* __restrict__ out)
{
    const int t = threadIdx.x;
    const int warp = t >> 5, lane = t & 31;

    const size_t base = (size_t)blockIdx.x * ROWS * D_VEC;
    const float4* x4 = reinterpret_cast<const float4*>(x) + base;

    // ---- Phase 0: all x loads upfront (8 independent LDG.128, MLP=8) ------
    float4 xa[ROWS], xb[ROWS];
#pragma unroll
    for (int r = 0; r < ROWS; ++r) {
        xa[r] = __ldcs(&x4[r * D_VEC + t]);
        xb[r] = __ldcs(&x4[r * D_VEC + t + TPB]);
    }

    // ---- Phase 1: layer-outer accumulation. v[0..23]=dots, v[24..29]=C, ----
    // prea/preb accumulate the bias prefix (becomes bsum for the epilogue).
    float v[32];
    v[30] = 0.f; v[31] = 0.f;
    float4 prea = make_float4(0.f, 0.f, 0.f, 0.f);
    float4 preb = make_float4(0.f, 0.f, 0.f, 0.f);
#pragma unroll
    for (int l = 0; l < L_DIM; ++l) {
        const float4* w4 = reinterpret_cast<const float4*>(W) + l * D_VEC;
        const float4* b4 = reinterpret_cast<const float4*>(b) + l * D_VEC;
        const float4 wa = __ldg(&w4[t]);
        const float4 wb = __ldg(&w4[t + TPB]);
        const float4 bva = __ldg(&b4[t]);
        const float4 bvb = __ldg(&b4[t + TPB]);

        // C_l partial: (prefix of b before layer l) . W_l
        v[NVAL + l] = prea.x * wa.x + prea.y * wa.y
                    + prea.z * wa.z + prea.w * wa.w
                    + preb.x * wb.x + preb.y * wb.y
                    + preb.z * wb.z + preb.w * wb.w;
        prea.x += bva.x; prea.y += bva.y; prea.z += bva.z; prea.w += bva.w;
        preb.x += bvb.x; preb.y += bvb.y; preb.z += bvb.z; preb.w += bvb.w;

#pragma unroll
        for (int r = 0; r < ROWS; ++r) {
            v[r * L_DIM + l] =
                  xa[r].x * wa.x + xa[r].y * wa.y
                + xa[r].z * wa.z + xa[r].w * wa.w
                + xb[r].x * wb.x + xb[r].y * wb.y
                + xb[r].z * wb.z + xb[r].w * wb.w;
        }
    }

    // ---- Batched pair-merge warp reduction: 31 shuffles for 32 sums. ------
    // Final: lane L holds the complete warp-sum of value L in v[0].
#pragma unroll
    for (int d = 16; d >= 1; d >>= 1) {
#pragma unroll
        for (int i = 0; i < d; ++i) {
            const float send = (lane & d) ? v[i] : v[i + d];
            const float got = __shfl_xor_sync(0xffffffffu, send, d);
            v[i] = ((lane & d) ? v[i + d] : v[i]) + got;
        }
    }

    __shared__ float sred[NWARP][32];
    __shared__ __align__(16) float sd[32];
    if (lane < NRED) sred[warp][lane] = v[0];
    __syncthreads();

    // ---- Cross-warp: warp0 sums 8 partials per value (conflict-free). -----
    if (warp == 0 && lane < NRED) {
        float acc = 0.f;
#pragma unroll
        for (int w = 0; w < NWARP; ++w) acc += sred[w][lane];
        sd[lane] = acc;
    }
    __syncthreads();

    // ---- Phase 2: broadcast 30 values via 8 LDS.128, alphas, store. -------
    const float4* sd4 = reinterpret_cast<const float4*>(sd);
    float ds[32];
#pragma unroll
    for (int q = 0; q < 8; ++q) {
        const float4 dv = sd4[q];
        ds[q * 4 + 0] = dv.x;  ds[q * 4 + 1] = dv.y;
        ds[q * 4 + 2] = dv.z;  ds[q * 4 + 3] = dv.w;
    }
    // ds[0..23] = dots, ds[24..29] = C_l.

    float4* o4 = reinterpret_cast<float4*>(out) + base;
#pragma unroll
    for (int r = 0; r < ROWS; ++r) {
        float a = 1.f;
#pragma unroll
        for (int l = 0; l < L_DIM; ++l)
            a += a * ds[r * L_DIM + l] + ds[NVAL + l];

        float4 oa, ob;
        oa.x = a * xa[r].x + prea.x;  oa.y = a * xa[r].y + prea.y;
        oa.z = a * xa[r].z + prea.z;  oa.w = a * xa[r].w + prea.w;
        ob.x = a * xb[r].x + preb.x;  ob.y = a * xb[r].y + preb.y;
        ob.z = a * xb[r].z + preb.z;  ob.w = a * xb[r].w + preb.w;
        __stcs(&o4[r * D_VEC + t], oa);
        __stcs(&o4[r * D_VEC + t + TPB], ob);
    }
}

// ---------------------------------------------------------------------------
extern "C" void kernel_launch(void* const* d_in, const int* in_sizes, int n_in,
                              void* d_out, int out_size)
{
    const float* x = (const float*)d_in[0];   // [B, 2048]
    const float* W = (const float*)d_in[1];   // [6, 2048]
    const float* b = (const float*)d_in[2];   // [6, 2048]
    float* out = (float*)d_out;               // [B, 2048]

    const int B = in_sizes[0] / D_DIM;

    cross_kernel<<<B / ROWS, TPB>>>(x, W, b, out);
}